// round 11
// baseline (speedup 1.0000x reference)
#include <cuda_runtime.h>
#include <cuda_bf16.h>
#include <cuda_fp16.h>
#include <stdint.h>

#define NB   8
#define MM   2048
#define DIN  64
#define DH   128
#define NODES (NB*MM)
#define KSPLIT 2

// scratch for gx as fp16, layout [n][i][h]
__device__ __align__(16) __half g_gh[NODES * DH];

// prepped split-bf16 weights for stage1, smem-identical layout [64][W_LDT]
#define W_LDT  136
__device__ __align__(16) __nv_bfloat16 pw_hi[5][64 * W_LDT];
__device__ __align__(16) __nv_bfloat16 pw_lo[5][64 * W_LDT];

// ---------------------------------------------------------------------------
#define LDSM_X4(r0,r1,r2,r3,addr) \
    asm volatile("ldmatrix.sync.aligned.m8n8.x4.shared.b16 {%0,%1,%2,%3}, [%4];" \
        : "=r"(r0),"=r"(r1),"=r"(r2),"=r"(r3) : "r"(addr))
#define LDSM_X4_T(r0,r1,r2,r3,addr) \
    asm volatile("ldmatrix.sync.aligned.m8n8.x4.trans.shared.b16 {%0,%1,%2,%3}, [%4];" \
        : "=r"(r0),"=r"(r1),"=r"(r2),"=r"(r3) : "r"(addr))
#define MMA16816(c,a,b) \
    asm volatile("mma.sync.aligned.m16n8k16.row.col.f32.bf16.bf16.f32 " \
        "{%0,%1,%2,%3}, {%4,%5,%6,%7}, {%8,%9}, {%0,%1,%2,%3};" \
        : "+f"(c[0]),"+f"(c[1]),"+f"(c[2]),"+f"(c[3]) \
        : "r"(a[0]),"r"(a[1]),"r"(a[2]),"r"(a[3]),"r"(b[0]),"r"(b[1]))
#define MMAF16(c,a,b) \
    asm volatile("mma.sync.aligned.m16n8k16.row.col.f32.f16.f16.f32 " \
        "{%0,%1,%2,%3}, {%4,%5,%6,%7}, {%8,%9}, {%0,%1,%2,%3};" \
        : "+f"(c[0]),"+f"(c[1]),"+f"(c[2]),"+f"(c[3]) \
        : "r"(a[0]),"r"(a[1]),"r"(a[2]),"r"(a[3]),"r"(b[0]),"r"(b[1]))
#define CP_ASYNC16(dst,src) \
    asm volatile("cp.async.cg.shared.global [%0], [%1], 16;" :: "r"(dst), "l"(src))
#define CP_COMMIT() asm volatile("cp.async.commit_group;")
#define CP_WAIT0()  asm volatile("cp.async.wait_group 0;")
#define CP_WAIT1()  asm volatile("cp.async.wait_group 1;")

__device__ __forceinline__ void split2(float v0, float v1, uint32_t& hi, uint32_t& lo)
{
    __nv_bfloat16 h0 = __float2bfloat16(v0);
    __nv_bfloat16 h1 = __float2bfloat16(v1);
    __nv_bfloat16 l0 = __float2bfloat16(v0 - __bfloat162float(h0));
    __nv_bfloat16 l1 = __float2bfloat16(v1 - __bfloat162float(h1));
    hi = (uint32_t)__bfloat16_as_ushort(h0) | ((uint32_t)__bfloat16_as_ushort(h1) << 16);
    lo = (uint32_t)__bfloat16_as_ushort(l0) | ((uint32_t)__bfloat16_as_ushort(l1) << 16);
}

__device__ __forceinline__ uint32_t pack_h2(float a, float b)
{
    __half2 h = __floats2half2_rn(a, b);
    return *(uint32_t*)&h;
}

// ===========================================================================
// Weight prep: fp32 weights -> split-bf16 planes (g_w1 collapsed, g_w2 halved)
// layers: 0=f1(64x64) 1=f2(64x128) 2=g1c(64x128) 3=g2[0:64] 4=g2[64:128]
// ===========================================================================
__global__ void prep_kernel(
    const float* __restrict__ fw1, const float* __restrict__ fw2,
    const float* __restrict__ gw1, const float* __restrict__ gw2)
{
    const int tot = 2048 + 4*4096;   // col-pairs
    for (int idx = blockIdx.x*blockDim.x + threadIdx.x; idx < tot;
         idx += gridDim.x*blockDim.x) {
        int layer, rem, N;
        if (idx < 2048) { layer = 0; rem = idx; N = 64; }
        else { int r = idx - 2048; layer = 1 + (r >> 12); rem = r & 4095; N = 128; }
        int k  = rem / (N/2);
        int n2 = (rem - k*(N/2)) * 2;
        float v0, v1;
        switch (layer) {
            case 0: v0 = fw1[k*64 + n2];  v1 = fw1[k*64 + n2 + 1];  break;
            case 1: v0 = fw2[k*128 + n2]; v1 = fw2[k*128 + n2 + 1]; break;
            case 2: v0 = gw1[k*128 + n2] + gw1[(k + 64)*128 + n2];
                    v1 = gw1[k*128 + n2 + 1] + gw1[(k + 64)*128 + n2 + 1]; break;
            case 3: v0 = gw2[k*128 + n2]; v1 = gw2[k*128 + n2 + 1]; break;
            default: v0 = gw2[(k + 64)*128 + n2]; v1 = gw2[(k + 64)*128 + n2 + 1]; break;
        }
        uint32_t hi, lo;
        split2(v0, v1, hi, lo);
        *(uint32_t*)&pw_hi[layer][k*W_LDT + n2] = hi;
        *(uint32_t*)&pw_lo[layer][k*W_LDT + n2] = lo;
    }
}

// ===========================================================================
// Stage 1: 128-thread blocks, 32 node-rows, double-buffered weights with
// deferred cp.async waits (each wait covered by the previous layer's MMAs).
// f-path blocks (0..511) and g-path blocks (512..1023).
// ===========================================================================
#define S1_T   128
#define S1_R   32
#define A0_LDT 72
#define A1_LDT 136
#define W_PS   (64*W_LDT)
#define A0_PS  (S1_R*A0_LDT)
#define A1_PS  (S1_R*A1_LDT)

template<int NFR>
__device__ __forceinline__ void mma_pass(
    float acc[2][NFR][4],
    uint32_t aHiA, uint32_t aLoA, int aLDT, int kColOfs,
    uint32_t wHiA, uint32_t wLoA,
    int lane, int wn)
{
    const int arow = lane & 15;
    const int aq   = ((lane >> 4) & 1) * 8;
    const int bq   = ((lane >> 4) & 1) * 8;
    #pragma unroll
    for (int ks = 0; ks < 4; ks++) {
        uint32_t ah[2][4], al[2][4];
        #pragma unroll
        for (int mf = 0; mf < 2; mf++) {
            uint32_t ao = (uint32_t)(((arow + mf*16)*aLDT + kColOfs + ks*16 + aq) * 2);
            LDSM_X4(ah[mf][0], ah[mf][1], ah[mf][2], ah[mf][3], aHiA + ao);
            LDSM_X4(al[mf][0], al[mf][1], al[mf][2], al[mf][3], aLoA + ao);
        }
        uint32_t bh[(NFR+1)/2][4], bl[(NFR+1)/2][4];
        #pragma unroll
        for (int nf2 = 0; nf2 < (NFR+1)/2; nf2++) {
            uint32_t bo = (uint32_t)((((ks*16) + (lane & 15))*W_LDT + wn*NFR*8 + nf2*16 + bq) * 2);
            LDSM_X4_T(bh[nf2][0], bh[nf2][1], bh[nf2][2], bh[nf2][3], wHiA + bo);
            LDSM_X4_T(bl[nf2][0], bl[nf2][1], bl[nf2][2], bl[nf2][3], wLoA + bo);
        }
        #pragma unroll
        for (int mf = 0; mf < 2; mf++)
            #pragma unroll
            for (int nf = 0; nf < NFR; nf++) {
                uint32_t* bhf = &bh[nf>>1][(nf&1)*2];
                uint32_t* blf = &bl[nf>>1][(nf&1)*2];
                MMA16816(acc[mf][nf], ah[mf], bhf);
                MMA16816(acc[mf][nf], ah[mf], blf);
                MMA16816(acc[mf][nf], al[mf], bhf);
            }
    }
}

template<int NFR>
__device__ __forceinline__ void init_bias(float acc[2][NFR][4],
    const float* __restrict__ b, int lane, int wn)
{
    #pragma unroll
    for (int nf = 0; nf < NFR; nf++) {
        int c = wn*NFR*8 + nf*8 + (lane & 3)*2;
        float b0 = b[c], b1 = b[c + 1];
        #pragma unroll
        for (int mf = 0; mf < 2; mf++) {
            acc[mf][nf][0] = b0; acc[mf][nf][1] = b1;
            acc[mf][nf][2] = b0; acc[mf][nf][3] = b1;
        }
    }
}

template<int NFR>
__device__ __forceinline__ void epi_relu_split(float acc[2][NFR][4],
    __nv_bfloat16* dHi, __nv_bfloat16* dLo, int ldt, int lane, int wn)
{
    #pragma unroll
    for (int mf = 0; mf < 2; mf++) {
        int r0 = mf*16 + (lane >> 2);
        #pragma unroll
        for (int nf = 0; nf < NFR; nf++) {
            int c = wn*NFR*8 + nf*8 + (lane & 3)*2;
            uint32_t hi, lo;
            split2(fmaxf(acc[mf][nf][0], 0.f), fmaxf(acc[mf][nf][1], 0.f), hi, lo);
            *(uint32_t*)&dHi[r0*ldt + c] = hi;
            *(uint32_t*)&dLo[r0*ldt + c] = lo;
            split2(fmaxf(acc[mf][nf][2], 0.f), fmaxf(acc[mf][nf][3], 0.f), hi, lo);
            *(uint32_t*)&dHi[(r0 + 8)*ldt + c] = hi;
            *(uint32_t*)&dLo[(r0 + 8)*ldt + c] = lo;
        }
    }
}

// issue-only async copy of a prepped weight layer (hi+lo) into smem; 1 group
__device__ __forceinline__ void weight_issue(int layer,
    uint32_t wHiA, uint32_t wLoA, int t)
{
    const uint8_t* srcH = (const uint8_t*)pw_hi[layer];
    const uint8_t* srcL = (const uint8_t*)pw_lo[layer];
    for (int idx = t; idx < (64*W_LDT*2)/16; idx += S1_T) {   // 1088
        CP_ASYNC16(wHiA + idx*16, srcH + idx*16);
        CP_ASYNC16(wLoA + idx*16, srcL + idx*16);
    }
    CP_COMMIT();
}

__global__ __launch_bounds__(S1_T) void stage1_kernel(
    const float* __restrict__ x,
    const float* __restrict__ fb1, const float* __restrict__ fb2,
    const float* __restrict__ gb1, const float* __restrict__ gb2,
    float* __restrict__ out)
{
    extern __shared__ __nv_bfloat16 s1[];
    __nv_bfloat16* wAHi = s1;
    __nv_bfloat16* wALo = wAHi + W_PS;
    __nv_bfloat16* wBHi = wALo + W_PS;
    __nv_bfloat16* wBLo = wBHi + W_PS;
    __nv_bfloat16* a0Hi = wBLo + W_PS;
    __nv_bfloat16* a0Lo = a0Hi + A0_PS;
    __nv_bfloat16* a1Hi = a0Lo + A0_PS;
    __nv_bfloat16* a1Lo = a1Hi + A1_PS;

    const int t = threadIdx.x, lane = t & 31, wid = t >> 5;
    const int wn = wid & 3;
    const bool fpath = (blockIdx.x < 512);
    const int nodeBase = (blockIdx.x & 511) * S1_R;

    const uint32_t wAHiA = (uint32_t)__cvta_generic_to_shared(wAHi);
    const uint32_t wALoA = (uint32_t)__cvta_generic_to_shared(wALo);
    const uint32_t wBHiA = (uint32_t)__cvta_generic_to_shared(wBHi);
    const uint32_t wBLoA = (uint32_t)__cvta_generic_to_shared(wBLo);
    const uint32_t a0HiA = (uint32_t)__cvta_generic_to_shared(a0Hi);
    const uint32_t a0LoA = (uint32_t)__cvta_generic_to_shared(a0Lo);
    const uint32_t a1HiA = (uint32_t)__cvta_generic_to_shared(a1Hi);
    const uint32_t a1LoA = (uint32_t)__cvta_generic_to_shared(a1Lo);

    // issue both layer weight loads up-front (groups 0 and 1)
    weight_issue(fpath ? 0 : 2, wAHiA, wALoA, t);
    weight_issue(fpath ? 1 : 3, wBHiA, wBLoA, t);

    // x tile [32 x 64] split (plain LD/ST, overlaps with weight cp.async)
    for (int idx = t; idx < S1_R*64/2; idx += S1_T) {
        int r  = idx >> 5;
        int c2 = (idx & 31) * 2;
        float2 v = *(const float2*)&x[(size_t)(nodeBase + r)*DIN + c2];
        uint32_t hi, lo;
        split2(v.x, v.y, hi, lo);
        *(uint32_t*)&a0Hi[r*A0_LDT + c2] = hi;
        *(uint32_t*)&a0Lo[r*A0_LDT + c2] = lo;
    }

    if (fpath) {
        CP_WAIT1();            // W0 arrived (W1 may pend)
        __syncthreads();
        {   // f1 (wA)
            float acc[2][2][4];
            init_bias<2>(acc, fb1, lane, wn);
            mma_pass<2>(acc, a0HiA, a0LoA, A0_LDT, 0, wAHiA, wALoA, lane, wn);
            epi_relu_split<2>(acc, a1Hi, a1Lo, A1_LDT, lane, wn);
        }
        CP_WAIT0();            // W1 arrived (covered by f1 compute)
        __syncthreads();
        {   // f2 (wB) -> out
            float acc[2][4][4];
            init_bias<4>(acc, fb2, lane, wn);
            mma_pass<4>(acc, a1HiA, a1LoA, A1_LDT, 0, wBHiA, wBLoA, lane, wn);
            #pragma unroll
            for (int mf = 0; mf < 2; mf++) {
                int r0 = nodeBase + mf*16 + (lane >> 2);
                #pragma unroll
                for (int nf = 0; nf < 4; nf++) {
                    int c = wn*32 + nf*8 + (lane & 3)*2;
                    *(float2*)&out[(size_t)r0*DH + c]       = make_float2(acc[mf][nf][0], acc[mf][nf][1]);
                    *(float2*)&out[(size_t)(r0 + 8)*DH + c] = make_float2(acc[mf][nf][2], acc[mf][nf][3]);
                }
            }
        }
    } else {
        CP_WAIT1();            // W2 arrived
        __syncthreads();
        {   // g1 (wA, collapsed g_w1)
            float acc[2][4][4];
            init_bias<4>(acc, gb1, lane, wn);
            mma_pass<4>(acc, a0HiA, a0LoA, A0_LDT, 0, wAHiA, wALoA, lane, wn);
            epi_relu_split<4>(acc, a1Hi, a1Lo, A1_LDT, lane, wn);
        }
        __syncthreads();       // a1 visible; all warps done with wA
        weight_issue(4, wAHiA, wALoA, t);   // W4 -> wA (group 2)

        float acc[2][4][4];
        init_bias<4>(acc, gb2, lane, wn);
        // g2a (wB = g2 rows 0..63)
        CP_WAIT1();
        mma_pass<4>(acc, a1HiA, a1LoA, A1_LDT, 0, wBHiA, wBLoA, lane, wn);
        CP_WAIT0();            // W4 arrived (covered by g2a compute)
        __syncthreads();
        // g2b (wA = g2 rows 64..127)
        mma_pass<4>(acc, a1HiA, a1LoA, A1_LDT, 64, wAHiA, wALoA, lane, wn);

        // epilogue: single fp16 plane -> g_gh [n][i][h] (coalesced)
        #pragma unroll
        for (int mf = 0; mf < 2; mf++) {
            int r0 = nodeBase + mf*16 + (lane >> 2);
            #pragma unroll
            for (int nf = 0; nf < 4; nf++) {
                int c = wn*32 + nf*8 + (lane & 3)*2;
                *(uint32_t*)&g_gh[(size_t)r0*DH + c] =
                    pack_h2(acc[mf][nf][0], acc[mf][nf][1]);
                *(uint32_t*)&g_gh[(size_t)(r0 + 8)*DH + c] =
                    pack_h2(acc[mf][nf][2], acc[mf][nf][3]);
            }
        }
    }
}

// ===========================================================================
// Stage 2 (pure fp16 1-term, 3-stage pipeline, SINGLE WAVE):
// out[n,j,h] += sum_i edge[n,i,j]*gx[n,i,h]
// grid (32, 8, KSPLIT=2) = 512 blocks, all resident (launch_bounds(256,4)
// caps regs at 64 so 4 CTAs/SM fit the register file). K=1024 per block.
// G cp.async 2 chunks ahead (wait_group 1); E register-prefetch distance 2.
// Epilogue: atomicAdd into out (RED.ADD, 2 commutative contributors).
// ===========================================================================
#define BK    32
#define EPAD  72
#define GPAD  136
#define SE_PS (BK*EPAD)
#define SG_PS (BK*GPAD)
#define KITER (MM/(BK*KSPLIT))     // 32

__global__ __launch_bounds__(256, 4) void stage2_kernel(
    const float* __restrict__ edge, float* __restrict__ out)
{
    extern __shared__ __half sm2[];
    __half* sE = sm2;                   // [3 buf][BK][EPAD]
    __half* sG = sm2 + 3*SE_PS;         // [3 buf][BK][GPAD]

    const int n  = blockIdx.y;
    const int j0 = blockIdx.x * 64;
    const int kz = blockIdx.z;
    const int koff = kz * (MM / KSPLIT);
    const int t = threadIdx.x, lane = t & 31, wid = t >> 5;
    const int wm = wid >> 2, wn = wid & 3;

    const float* eg = edge + (size_t)n*MM*MM + j0;
    const __half* gh = g_gh + (size_t)n*MM*DH;

    const uint32_t sEb = (uint32_t)__cvta_generic_to_shared(sE);
    const uint32_t sGb = (uint32_t)__cvta_generic_to_shared(sG);

    const int ldrow = t >> 4;          // 0..15 (and +16)
    const int ecol  = (t & 15) * 4;
    const int gcol  = (t & 15) * 8;

    const int arow_off = ((lane >> 4) & 1)*8 + (lane & 7);
    const int aq1      = ((lane >> 3) & 1)*8;
    const int bq       = ((lane >> 4) & 1)*8;

    float acc[2][4][4];
    #pragma unroll
    for (int a = 0; a < 2; a++)
        #pragma unroll
        for (int b = 0; b < 4; b++)
            #pragma unroll
            for (int c = 0; c < 4; c++) acc[a][b][c] = 0.f;

    float4 erA[2], erB[2];

    // ---- prologue ----
    // G chunks 0,1 -> gbuf 0,1 (groups 0,1)
    #pragma unroll
    for (int c = 0; c < 2; c++) {
        #pragma unroll
        for (int u = 0; u < 2; u++) {
            int row = ldrow + u*16;
            CP_ASYNC16(sGb + (uint32_t)((c*BK + row)*GPAD + gcol)*2,
                       gh + (size_t)(koff + c*BK + row)*DH + gcol);
        }
        CP_COMMIT();
    }
    // E chunk 0: LDG -> regs -> STS ebuf0 (one exposed load, prologue only)
    #pragma unroll
    for (int u = 0; u < 2; u++)
        erA[u] = *(const float4*)&eg[(size_t)(koff + ldrow + u*16)*MM + ecol];
    #pragma unroll
    for (int u = 0; u < 2; u++) {
        int row = ldrow + u*16;
        float4 v = erA[u];
        *(uint2*)&sE[(0*BK + row)*EPAD + ecol] =
            make_uint2(pack_h2(v.x, v.y), pack_h2(v.z, v.w));
    }
    // E chunks 1,2 -> regs
    #pragma unroll
    for (int u = 0; u < 2; u++)
        erA[u] = *(const float4*)&eg[(size_t)(koff + 1*BK + ldrow + u*16)*MM + ecol];
    #pragma unroll
    for (int u = 0; u < 2; u++)
        erB[u] = *(const float4*)&eg[(size_t)(koff + 2*BK + ldrow + u*16)*MM + ecol];

    CP_WAIT1();          // G chunk 0 arrived
    __syncthreads();

    for (int kt = 0; kt < KITER; kt++) {
        const int b = kt % 3;

        // 1. G prefetch chunk kt+2 into gbuf (kt+2)%3
        if (kt + 2 < KITER) {
            const int i0 = koff + (kt + 2) * BK;
            const int gb = (kt + 2) % 3;
            #pragma unroll
            for (int u = 0; u < 2; u++) {
                int row = ldrow + u*16;
                CP_ASYNC16(sGb + (uint32_t)((gb*BK + row)*GPAD + gcol)*2,
                           gh + (size_t)(i0 + row)*DH + gcol);
            }
            CP_COMMIT();
        }

        // 2. store E chunk kt+1 (erA) into ebuf (kt+1)%3
        if (kt + 1 < KITER) {
            const int eb = (kt + 1) % 3;
            #pragma unroll
            for (int u = 0; u < 2; u++) {
                int row = ldrow + u*16;
                float4 v = erA[u];
                *(uint2*)&sE[(eb*BK + row)*EPAD + ecol] =
                    make_uint2(pack_h2(v.x, v.y), pack_h2(v.z, v.w));
            }
        }

        // 3. shift regs; LDG E chunk kt+3 into erB (distance-2 prefetch)
        erA[0] = erB[0]; erA[1] = erB[1];
        if (kt + 3 < KITER) {
            const int i0 = koff + (kt + 3) * BK;
            #pragma unroll
            for (int u = 0; u < 2; u++)
                erB[u] = *(const float4*)&eg[(size_t)(i0 + ldrow + u*16)*MM + ecol];
        }

        // 4. compute on buffer b
        #pragma unroll
        for (int ks = 0; ks < BK; ks += 16) {
            uint32_t ah[2][4];
            #pragma unroll
            for (int mf = 0; mf < 2; mf++) {
                int acol = wm*32 + mf*16 + aq1;
                uint32_t a0 = sEb + (uint32_t)(((b*BK + ks + arow_off)*EPAD + acol)*2);
                LDSM_X4_T(ah[mf][0], ah[mf][1], ah[mf][2], ah[mf][3], a0);
            }
            uint32_t bh[2][4];
            #pragma unroll
            for (int nf2 = 0; nf2 < 2; nf2++) {
                int bcol = wn*32 + nf2*16 + bq;
                uint32_t b0 = sGb + (uint32_t)(((b*BK + ks + (lane & 15))*GPAD + bcol)*2);
                LDSM_X4_T(bh[nf2][0], bh[nf2][1], bh[nf2][2], bh[nf2][3], b0);
            }
            #pragma unroll
            for (int mf = 0; mf < 2; mf++)
                #pragma unroll
                for (int nf = 0; nf < 4; nf++) {
                    uint32_t* bhf = &bh[nf>>1][(nf&1)*2];
                    MMAF16(acc[mf][nf], ah[mf], bhf);
                }
        }

        // 5. G chunk kt+1 must have arrived (kt+2 group may pend)
        CP_WAIT1();
        __syncthreads();
    }

    // epilogue: atomic add into out (commutative across K-halves)
    #pragma unroll
    for (int mf = 0; mf < 2; mf++) {
        int r0 = j0 + wm*32 + mf*16 + (lane >> 2);
        #pragma unroll
        for (int nf = 0; nf < 4; nf++) {
            int c = wn*32 + nf*8 + (lane & 3)*2;
            size_t o0 = ((size_t)n*MM + r0)*DH + c;
            size_t o1 = o0 + (size_t)8*DH;
            atomicAdd(&out[o0],     acc[mf][nf][0]);
            atomicAdd(&out[o0 + 1], acc[mf][nf][1]);
            atomicAdd(&out[o1],     acc[mf][nf][2]);
            atomicAdd(&out[o1 + 1], acc[mf][nf][3]);
        }
    }
}

// ---------------------------------------------------------------------------
extern "C" void kernel_launch(void* const* d_in, const int* in_sizes, int n_in,
                              void* d_out, int out_size)
{
    const float* x    = (const float*)d_in[0];
    const float* edge = (const float*)d_in[1];
    const float* fw1  = (const float*)d_in[2];
    const float* fb1  = (const float*)d_in[3];
    const float* fw2  = (const float*)d_in[4];
    const float* fb2  = (const float*)d_in[5];
    const float* gw1  = (const float*)d_in[6];
    const float* gb1  = (const float*)d_in[7];
    const float* gw2  = (const float*)d_in[8];
    const float* gb2  = (const float*)d_in[9];
    float* out = (float*)d_out;

    const int SMEM1 = (4*W_PS + 2*A0_PS + 2*A1_PS) * 2;   // 96256 B
    const int SMEM2 = (3*SE_PS + 3*SG_PS) * 2;            // 39936 B

    cudaFuncSetAttribute(stage1_kernel, cudaFuncAttributeMaxDynamicSharedMemorySize, SMEM1);
    cudaFuncSetAttribute(stage2_kernel, cudaFuncAttributeMaxDynamicSharedMemorySize, SMEM2);

    prep_kernel<<<144, 256>>>(fw1, fw2, gw1, gw2);
    stage1_kernel<<<1024, S1_T, SMEM1>>>(x, fb1, fb2, gb1, gb2, out);
    stage2_kernel<<<dim3(32, NB, KSPLIT), 256, SMEM2>>>(edge, out);
}

// round 13
// speedup vs baseline: 1.1091x; 1.1091x over previous
#include <cuda_runtime.h>
#include <cuda_bf16.h>
#include <cuda_fp16.h>
#include <stdint.h>

#define NB   8
#define MM   2048
#define DIN  64
#define DH   128
#define NODES (NB*MM)
#define KSPLIT 4

// scratch for gx as fp16, layout [n][i][h]
__device__ __align__(16) __half g_gh[NODES * DH];

// prepped weights: f layers split-bf16 (0=f1 64x64, 1=f2 64x128),
// g layers single fp16 (0=g1c, 1=g2[0:64], 2=g2[64:128])
#define W_LDT  136
__device__ __align__(16) __nv_bfloat16 pw_hi[2][64 * W_LDT];
__device__ __align__(16) __nv_bfloat16 pw_lo[2][64 * W_LDT];
__device__ __align__(16) __half        pw_g [3][64 * W_LDT];

// ---------------------------------------------------------------------------
#define LDSM_X4(r0,r1,r2,r3,addr) \
    asm volatile("ldmatrix.sync.aligned.m8n8.x4.shared.b16 {%0,%1,%2,%3}, [%4];" \
        : "=r"(r0),"=r"(r1),"=r"(r2),"=r"(r3) : "r"(addr))
#define LDSM_X4_T(r0,r1,r2,r3,addr) \
    asm volatile("ldmatrix.sync.aligned.m8n8.x4.trans.shared.b16 {%0,%1,%2,%3}, [%4];" \
        : "=r"(r0),"=r"(r1),"=r"(r2),"=r"(r3) : "r"(addr))
#define MMA16816(c,a,b) \
    asm volatile("mma.sync.aligned.m16n8k16.row.col.f32.bf16.bf16.f32 " \
        "{%0,%1,%2,%3}, {%4,%5,%6,%7}, {%8,%9}, {%0,%1,%2,%3};" \
        : "+f"(c[0]),"+f"(c[1]),"+f"(c[2]),"+f"(c[3]) \
        : "r"(a[0]),"r"(a[1]),"r"(a[2]),"r"(a[3]),"r"(b[0]),"r"(b[1]))
#define MMAF16(c,a,b) \
    asm volatile("mma.sync.aligned.m16n8k16.row.col.f32.f16.f16.f32 " \
        "{%0,%1,%2,%3}, {%4,%5,%6,%7}, {%8,%9}, {%0,%1,%2,%3};" \
        : "+f"(c[0]),"+f"(c[1]),"+f"(c[2]),"+f"(c[3]) \
        : "r"(a[0]),"r"(a[1]),"r"(a[2]),"r"(a[3]),"r"(b[0]),"r"(b[1]))
#define CP_ASYNC16(dst,src) \
    asm volatile("cp.async.cg.shared.global [%0], [%1], 16;" :: "r"(dst), "l"(src))
#define CP_COMMIT() asm volatile("cp.async.commit_group;")
#define CP_WAIT0()  asm volatile("cp.async.wait_group 0;")
#define CP_WAIT1()  asm volatile("cp.async.wait_group 1;")

__device__ __forceinline__ void split2(float v0, float v1, uint32_t& hi, uint32_t& lo)
{
    __nv_bfloat16 h0 = __float2bfloat16(v0);
    __nv_bfloat16 h1 = __float2bfloat16(v1);
    __nv_bfloat16 l0 = __float2bfloat16(v0 - __bfloat162float(h0));
    __nv_bfloat16 l1 = __float2bfloat16(v1 - __bfloat162float(h1));
    hi = (uint32_t)__bfloat16_as_ushort(h0) | ((uint32_t)__bfloat16_as_ushort(h1) << 16);
    lo = (uint32_t)__bfloat16_as_ushort(l0) | ((uint32_t)__bfloat16_as_ushort(l1) << 16);
}

__device__ __forceinline__ uint32_t pack_h2(float a, float b)
{
    __half2 h = __floats2half2_rn(a, b);
    return *(uint32_t*)&h;
}

// ===========================================================================
// Weight prep.
// idx < 2048          : f1 (bf16 split, N=64)
// idx < 6144          : f2 (bf16 split, N=128)
// else                : g layers (fp16 single, N=128): gl = 0..2
// ===========================================================================
__global__ void prep_kernel(
    const float* __restrict__ fw1, const float* __restrict__ fw2,
    const float* __restrict__ gw1, const float* __restrict__ gw2)
{
    const int tot = 2048 + 4096 + 3*4096;   // 18432 col-pairs
    for (int idx = blockIdx.x*blockDim.x + threadIdx.x; idx < tot;
         idx += gridDim.x*blockDim.x) {
        if (idx < 6144) {
            int layer, rem, N;
            if (idx < 2048) { layer = 0; rem = idx; N = 64; }
            else            { layer = 1; rem = idx - 2048; N = 128; }
            int k  = rem / (N/2);
            int n2 = (rem - k*(N/2)) * 2;
            float v0, v1;
            if (layer == 0) { v0 = fw1[k*64 + n2];  v1 = fw1[k*64 + n2 + 1]; }
            else            { v0 = fw2[k*128 + n2]; v1 = fw2[k*128 + n2 + 1]; }
            uint32_t hi, lo;
            split2(v0, v1, hi, lo);
            *(uint32_t*)&pw_hi[layer][k*W_LDT + n2] = hi;
            *(uint32_t*)&pw_lo[layer][k*W_LDT + n2] = lo;
        } else {
            int r   = idx - 6144;
            int gl  = r >> 12;
            int rem = r & 4095;
            int k   = rem >> 6;
            int n2  = (rem & 63) * 2;
            float v0, v1;
            if (gl == 0) {
                v0 = gw1[k*128 + n2]     + gw1[(k + 64)*128 + n2];
                v1 = gw1[k*128 + n2 + 1] + gw1[(k + 64)*128 + n2 + 1];
            } else if (gl == 1) {
                v0 = gw2[k*128 + n2];        v1 = gw2[k*128 + n2 + 1];
            } else {
                v0 = gw2[(k + 64)*128 + n2]; v1 = gw2[(k + 64)*128 + n2 + 1];
            }
            *(uint32_t*)&pw_g[gl][k*W_LDT + n2] = pack_h2(v0, v1);
        }
    }
}

// ===========================================================================
// Stage 1: 128-thread blocks, 32 node-rows.
// f-path blocks (0..511): split-bf16 3-term (precision -> out directly).
// g-path blocks (512..1023): pure fp16 single-term (gx stored fp16 anyway).
// ===========================================================================
#define S1_T   128
#define S1_R   32
#define A0_LDT 72
#define A1_LDT 136
#define W_PS   (64*W_LDT)
#define A0_PS  (S1_R*A0_LDT)
#define A1_PS  (S1_R*A1_LDT)

template<int NFR>
__device__ __forceinline__ void mma_pass(
    float acc[2][NFR][4],
    uint32_t aHiA, uint32_t aLoA, int aLDT, int kColOfs,
    uint32_t wHiA, uint32_t wLoA,
    int lane, int wn)
{
    const int arow = lane & 15;
    const int aq   = ((lane >> 4) & 1) * 8;
    #pragma unroll
    for (int ks = 0; ks < 4; ks++) {
        uint32_t ah[2][4], al[2][4];
        #pragma unroll
        for (int mf = 0; mf < 2; mf++) {
            uint32_t ao = (uint32_t)(((arow + mf*16)*aLDT + kColOfs + ks*16 + aq) * 2);
            LDSM_X4(ah[mf][0], ah[mf][1], ah[mf][2], ah[mf][3], aHiA + ao);
            LDSM_X4(al[mf][0], al[mf][1], al[mf][2], al[mf][3], aLoA + ao);
        }
        uint32_t bh[(NFR+1)/2][4], bl[(NFR+1)/2][4];
        #pragma unroll
        for (int nf2 = 0; nf2 < (NFR+1)/2; nf2++) {
            uint32_t bo = (uint32_t)((((ks*16) + (lane & 15))*W_LDT + wn*NFR*8 + nf2*16 + aq) * 2);
            LDSM_X4_T(bh[nf2][0], bh[nf2][1], bh[nf2][2], bh[nf2][3], wHiA + bo);
            LDSM_X4_T(bl[nf2][0], bl[nf2][1], bl[nf2][2], bl[nf2][3], wLoA + bo);
        }
        #pragma unroll
        for (int mf = 0; mf < 2; mf++)
            #pragma unroll
            for (int nf = 0; nf < NFR; nf++) {
                uint32_t* bhf = &bh[nf>>1][(nf&1)*2];
                uint32_t* blf = &bl[nf>>1][(nf&1)*2];
                MMA16816(acc[mf][nf], ah[mf], bhf);
                MMA16816(acc[mf][nf], ah[mf], blf);
                MMA16816(acc[mf][nf], al[mf], bhf);
            }
    }
}

// single-plane fp16 pass
template<int NFR>
__device__ __forceinline__ void mma_pass_f16(
    float acc[2][NFR][4],
    uint32_t aA, int aLDT, int kColOfs,
    uint32_t wA,
    int lane, int wn)
{
    const int arow = lane & 15;
    const int aq   = ((lane >> 4) & 1) * 8;
    #pragma unroll
    for (int ks = 0; ks < 4; ks++) {
        uint32_t ah[2][4];
        #pragma unroll
        for (int mf = 0; mf < 2; mf++) {
            uint32_t ao = (uint32_t)(((arow + mf*16)*aLDT + kColOfs + ks*16 + aq) * 2);
            LDSM_X4(ah[mf][0], ah[mf][1], ah[mf][2], ah[mf][3], aA + ao);
        }
        uint32_t bh[(NFR+1)/2][4];
        #pragma unroll
        for (int nf2 = 0; nf2 < (NFR+1)/2; nf2++) {
            uint32_t bo = (uint32_t)((((ks*16) + (lane & 15))*W_LDT + wn*NFR*8 + nf2*16 + aq) * 2);
            LDSM_X4_T(bh[nf2][0], bh[nf2][1], bh[nf2][2], bh[nf2][3], wA + bo);
        }
        #pragma unroll
        for (int mf = 0; mf < 2; mf++)
            #pragma unroll
            for (int nf = 0; nf < NFR; nf++) {
                uint32_t* bhf = &bh[nf>>1][(nf&1)*2];
                MMAF16(acc[mf][nf], ah[mf], bhf);
            }
    }
}

template<int NFR>
__device__ __forceinline__ void init_bias(float acc[2][NFR][4],
    const float* __restrict__ b, int lane, int wn)
{
    #pragma unroll
    for (int nf = 0; nf < NFR; nf++) {
        int c = wn*NFR*8 + nf*8 + (lane & 3)*2;
        float b0 = b[c], b1 = b[c + 1];
        #pragma unroll
        for (int mf = 0; mf < 2; mf++) {
            acc[mf][nf][0] = b0; acc[mf][nf][1] = b1;
            acc[mf][nf][2] = b0; acc[mf][nf][3] = b1;
        }
    }
}

template<int NFR>
__device__ __forceinline__ void epi_relu_split(float acc[2][NFR][4],
    __nv_bfloat16* dHi, __nv_bfloat16* dLo, int ldt, int lane, int wn)
{
    #pragma unroll
    for (int mf = 0; mf < 2; mf++) {
        int r0 = mf*16 + (lane >> 2);
        #pragma unroll
        for (int nf = 0; nf < NFR; nf++) {
            int c = wn*NFR*8 + nf*8 + (lane & 3)*2;
            uint32_t hi, lo;
            split2(fmaxf(acc[mf][nf][0], 0.f), fmaxf(acc[mf][nf][1], 0.f), hi, lo);
            *(uint32_t*)&dHi[r0*ldt + c] = hi;
            *(uint32_t*)&dLo[r0*ldt + c] = lo;
            split2(fmaxf(acc[mf][nf][2], 0.f), fmaxf(acc[mf][nf][3], 0.f), hi, lo);
            *(uint32_t*)&dHi[(r0 + 8)*ldt + c] = hi;
            *(uint32_t*)&dLo[(r0 + 8)*ldt + c] = lo;
        }
    }
}

template<int NFR>
__device__ __forceinline__ void epi_relu_f16(float acc[2][NFR][4],
    __half* d, int ldt, int lane, int wn)
{
    #pragma unroll
    for (int mf = 0; mf < 2; mf++) {
        int r0 = mf*16 + (lane >> 2);
        #pragma unroll
        for (int nf = 0; nf < NFR; nf++) {
            int c = wn*NFR*8 + nf*8 + (lane & 3)*2;
            *(uint32_t*)&d[r0*ldt + c] =
                pack_h2(fmaxf(acc[mf][nf][0], 0.f), fmaxf(acc[mf][nf][1], 0.f));
            *(uint32_t*)&d[(r0 + 8)*ldt + c] =
                pack_h2(fmaxf(acc[mf][nf][2], 0.f), fmaxf(acc[mf][nf][3], 0.f));
        }
    }
}

// issue-only async copy of a split-bf16 weight layer (hi+lo); 1 group
__device__ __forceinline__ void weight_issue(int layer,
    uint32_t wHiA, uint32_t wLoA, int t)
{
    const uint8_t* srcH = (const uint8_t*)pw_hi[layer];
    const uint8_t* srcL = (const uint8_t*)pw_lo[layer];
    for (int idx = t; idx < (64*W_LDT*2)/16; idx += S1_T) {   // 1088
        CP_ASYNC16(wHiA + idx*16, srcH + idx*16);
        CP_ASYNC16(wLoA + idx*16, srcL + idx*16);
    }
    CP_COMMIT();
}

// issue-only async copy of a single fp16 weight plane; 1 group
__device__ __forceinline__ void weight_issue_g(int layer, uint32_t wA, int t)
{
    const uint8_t* src = (const uint8_t*)pw_g[layer];
    for (int idx = t; idx < (64*W_LDT*2)/16; idx += S1_T)     // 1088
        CP_ASYNC16(wA + idx*16, src + idx*16);
    CP_COMMIT();
}

__global__ __launch_bounds__(S1_T) void stage1_kernel(
    const float* __restrict__ x,
    const float* __restrict__ fb1, const float* __restrict__ fb2,
    const float* __restrict__ gb1, const float* __restrict__ gb2,
    float* __restrict__ out)
{
    extern __shared__ __nv_bfloat16 s1[];

    const int t = threadIdx.x, lane = t & 31, wid = t >> 5;
    const int wn = wid & 3;
    const bool fpath = (blockIdx.x < 512);
    const int nodeBase = (blockIdx.x & 511) * S1_R;

    if (fpath) {
        __nv_bfloat16* wAHi = s1;
        __nv_bfloat16* wALo = wAHi + W_PS;
        __nv_bfloat16* wBHi = wALo + W_PS;
        __nv_bfloat16* wBLo = wBHi + W_PS;
        __nv_bfloat16* a0Hi = wBLo + W_PS;
        __nv_bfloat16* a0Lo = a0Hi + A0_PS;
        __nv_bfloat16* a1Hi = a0Lo + A0_PS;
        __nv_bfloat16* a1Lo = a1Hi + A1_PS;
        const uint32_t wAHiA = (uint32_t)__cvta_generic_to_shared(wAHi);
        const uint32_t wALoA = (uint32_t)__cvta_generic_to_shared(wALo);
        const uint32_t wBHiA = (uint32_t)__cvta_generic_to_shared(wBHi);
        const uint32_t wBLoA = (uint32_t)__cvta_generic_to_shared(wBLo);
        const uint32_t a0HiA = (uint32_t)__cvta_generic_to_shared(a0Hi);
        const uint32_t a0LoA = (uint32_t)__cvta_generic_to_shared(a0Lo);
        const uint32_t a1HiA = (uint32_t)__cvta_generic_to_shared(a1Hi);
        const uint32_t a1LoA = (uint32_t)__cvta_generic_to_shared(a1Lo);

        weight_issue(0, wAHiA, wALoA, t);   // grp0: f1
        weight_issue(1, wBHiA, wBLoA, t);   // grp1: f2

        // x tile [32 x 64] split bf16
        for (int idx = t; idx < S1_R*64/2; idx += S1_T) {
            int r  = idx >> 5;
            int c2 = (idx & 31) * 2;
            float2 v = *(const float2*)&x[(size_t)(nodeBase + r)*DIN + c2];
            uint32_t hi, lo;
            split2(v.x, v.y, hi, lo);
            *(uint32_t*)&a0Hi[r*A0_LDT + c2] = hi;
            *(uint32_t*)&a0Lo[r*A0_LDT + c2] = lo;
        }

        CP_WAIT1();
        __syncthreads();
        {   // f1 (wA)
            float acc[2][2][4];
            init_bias<2>(acc, fb1, lane, wn);
            mma_pass<2>(acc, a0HiA, a0LoA, A0_LDT, 0, wAHiA, wALoA, lane, wn);
            epi_relu_split<2>(acc, a1Hi, a1Lo, A1_LDT, lane, wn);
        }
        CP_WAIT0();
        __syncthreads();
        {   // f2 (wB) -> out
            float acc[2][4][4];
            init_bias<4>(acc, fb2, lane, wn);
            mma_pass<4>(acc, a1HiA, a1LoA, A1_LDT, 0, wBHiA, wBLoA, lane, wn);
            #pragma unroll
            for (int mf = 0; mf < 2; mf++) {
                int r0 = nodeBase + mf*16 + (lane >> 2);
                #pragma unroll
                for (int nf = 0; nf < 4; nf++) {
                    int c = wn*32 + nf*8 + (lane & 3)*2;
                    *(float2*)&out[(size_t)r0*DH + c]       = make_float2(acc[mf][nf][0], acc[mf][nf][1]);
                    *(float2*)&out[(size_t)(r0 + 8)*DH + c] = make_float2(acc[mf][nf][2], acc[mf][nf][3]);
                }
            }
        }
    } else {
        // ---- g-path: pure fp16 single-term ----
        __half* wGa = (__half*)s1;
        __half* wGb = (__half*)(s1 + W_PS);
        __half* a0h = (__half*)(s1 + 2*W_PS);
        __half* a1h = (__half*)(s1 + 2*W_PS + A0_PS);
        const uint32_t wGaA = (uint32_t)__cvta_generic_to_shared(wGa);
        const uint32_t wGbA = (uint32_t)__cvta_generic_to_shared(wGb);
        const uint32_t a0hA = (uint32_t)__cvta_generic_to_shared(a0h);
        const uint32_t a1hA = (uint32_t)__cvta_generic_to_shared(a1h);

        weight_issue_g(0, wGaA, t);   // grp0: g1c
        weight_issue_g(1, wGbA, t);   // grp1: g2 rows 0..63

        // x tile [32 x 64] fp16 single
        for (int idx = t; idx < S1_R*64/2; idx += S1_T) {
            int r  = idx >> 5;
            int c2 = (idx & 31) * 2;
            float2 v = *(const float2*)&x[(size_t)(nodeBase + r)*DIN + c2];
            *(uint32_t*)&a0h[r*A0_LDT + c2] = pack_h2(v.x, v.y);
        }

        CP_WAIT1();
        __syncthreads();
        {   // g1 (wGa)
            float acc[2][4][4];
            init_bias<4>(acc, gb1, lane, wn);
            mma_pass_f16<4>(acc, a0hA, A0_LDT, 0, wGaA, lane, wn);
            epi_relu_f16<4>(acc, a1h, A1_LDT, lane, wn);
        }
        __syncthreads();               // a1h visible; all warps done with wGa
        weight_issue_g(2, wGaA, t);    // grp2: g2 rows 64..127 -> wGa

        float acc[2][4][4];
        init_bias<4>(acc, gb2, lane, wn);
        CP_WAIT1();                    // grp1 (g2a) arrived
        __syncthreads();
        mma_pass_f16<4>(acc, a1hA, A1_LDT, 0, wGbA, lane, wn);
        CP_WAIT0();                    // grp2 (g2b) arrived (covered by g2a)
        __syncthreads();
        mma_pass_f16<4>(acc, a1hA, A1_LDT, 64, wGaA, lane, wn);

        // epilogue: fp16 -> g_gh [n][i][h] (coalesced)
        #pragma unroll
        for (int mf = 0; mf < 2; mf++) {
            int r0 = nodeBase + mf*16 + (lane >> 2);
            #pragma unroll
            for (int nf = 0; nf < 4; nf++) {
                int c = wn*32 + nf*8 + (lane & 3)*2;
                *(uint32_t*)&g_gh[(size_t)r0*DH + c] =
                    pack_h2(acc[mf][nf][0], acc[mf][nf][1]);
                *(uint32_t*)&g_gh[(size_t)(r0 + 8)*DH + c] =
                    pack_h2(acc[mf][nf][2], acc[mf][nf][3]);
            }
        }
    }
}

// ===========================================================================
// Stage 2 (pure fp16 1-term, 3-stage pipeline) — R10 configuration:
// out[n,j,h] += sum_i edge[n,i,j]*gx[n,i,h]
// grid (32, 8, KSPLIT=4): BM=64 x BN=128, BK=32.
// G cp.async 2 chunks ahead (wait_group 1); E register-prefetch distance 2.
// Epilogue: atomicAdd into out (RED.ADD, commutative across K-quarters).
// ===========================================================================
#define BK    32
#define EPAD  72
#define GPAD  136
#define SE_PS (BK*EPAD)
#define SG_PS (BK*GPAD)
#define KITER (MM/(BK*KSPLIT))     // 16

__global__ __launch_bounds__(256) void stage2_kernel(
    const float* __restrict__ edge, float* __restrict__ out)
{
    extern __shared__ __half sm2[];
    __half* sE = sm2;                   // [3 buf][BK][EPAD]
    __half* sG = sm2 + 3*SE_PS;         // [3 buf][BK][GPAD]

    const int n  = blockIdx.y;
    const int j0 = blockIdx.x * 64;
    const int kz = blockIdx.z;
    const int koff = kz * (MM / KSPLIT);
    const int t = threadIdx.x, lane = t & 31, wid = t >> 5;
    const int wm = wid >> 2, wn = wid & 3;

    const float* eg = edge + (size_t)n*MM*MM + j0;
    const __half* gh = g_gh + (size_t)n*MM*DH;

    const uint32_t sEb = (uint32_t)__cvta_generic_to_shared(sE);
    const uint32_t sGb = (uint32_t)__cvta_generic_to_shared(sG);

    const int ldrow = t >> 4;          // 0..15 (and +16)
    const int ecol  = (t & 15) * 4;
    const int gcol  = (t & 15) * 8;

    const int arow_off = ((lane >> 4) & 1)*8 + (lane & 7);
    const int aq1      = ((lane >> 3) & 1)*8;
    const int bq       = ((lane >> 4) & 1)*8;

    float acc[2][4][4];
    #pragma unroll
    for (int a = 0; a < 2; a++)
        #pragma unroll
        for (int b = 0; b < 4; b++)
            #pragma unroll
            for (int c = 0; c < 4; c++) acc[a][b][c] = 0.f;

    float4 erA[2], erB[2];

    // ---- prologue ----
    #pragma unroll
    for (int c = 0; c < 2; c++) {
        #pragma unroll
        for (int u = 0; u < 2; u++) {
            int row = ldrow + u*16;
            CP_ASYNC16(sGb + (uint32_t)((c*BK + row)*GPAD + gcol)*2,
                       gh + (size_t)(koff + c*BK + row)*DH + gcol);
        }
        CP_COMMIT();
    }
    #pragma unroll
    for (int u = 0; u < 2; u++)
        erA[u] = *(const float4*)&eg[(size_t)(koff + ldrow + u*16)*MM + ecol];
    #pragma unroll
    for (int u = 0; u < 2; u++) {
        int row = ldrow + u*16;
        float4 v = erA[u];
        *(uint2*)&sE[(0*BK + row)*EPAD + ecol] =
            make_uint2(pack_h2(v.x, v.y), pack_h2(v.z, v.w));
    }
    #pragma unroll
    for (int u = 0; u < 2; u++)
        erA[u] = *(const float4*)&eg[(size_t)(koff + 1*BK + ldrow + u*16)*MM + ecol];
    #pragma unroll
    for (int u = 0; u < 2; u++)
        erB[u] = *(const float4*)&eg[(size_t)(koff + 2*BK + ldrow + u*16)*MM + ecol];

    CP_WAIT1();
    __syncthreads();

    for (int kt = 0; kt < KITER; kt++) {
        const int b = kt % 3;

        if (kt + 2 < KITER) {
            const int i0 = koff + (kt + 2) * BK;
            const int gb = (kt + 2) % 3;
            #pragma unroll
            for (int u = 0; u < 2; u++) {
                int row = ldrow + u*16;
                CP_ASYNC16(sGb + (uint32_t)((gb*BK + row)*GPAD + gcol)*2,
                           gh + (size_t)(i0 + row)*DH + gcol);
            }
            CP_COMMIT();
        }

        if (kt + 1 < KITER) {
            const int eb = (kt + 1) % 3;
            #pragma unroll
            for (int u = 0; u < 2; u++) {
                int row = ldrow + u*16;
                float4 v = erA[u];
                *(uint2*)&sE[(eb*BK + row)*EPAD + ecol] =
                    make_uint2(pack_h2(v.x, v.y), pack_h2(v.z, v.w));
            }
        }

        erA[0] = erB[0]; erA[1] = erB[1];
        if (kt + 3 < KITER) {
            const int i0 = koff + (kt + 3) * BK;
            #pragma unroll
            for (int u = 0; u < 2; u++)
                erB[u] = *(const float4*)&eg[(size_t)(i0 + ldrow + u*16)*MM + ecol];
        }

        #pragma unroll
        for (int ks = 0; ks < BK; ks += 16) {
            uint32_t ah[2][4];
            #pragma unroll
            for (int mf = 0; mf < 2; mf++) {
                int acol = wm*32 + mf*16 + aq1;
                uint32_t a0 = sEb + (uint32_t)(((b*BK + ks + arow_off)*EPAD + acol)*2);
                LDSM_X4_T(ah[mf][0], ah[mf][1], ah[mf][2], ah[mf][3], a0);
            }
            uint32_t bh[2][4];
            #pragma unroll
            for (int nf2 = 0; nf2 < 2; nf2++) {
                int bcol = wn*32 + nf2*16 + bq;
                uint32_t b0 = sGb + (uint32_t)(((b*BK + ks + (lane & 15))*GPAD + bcol)*2);
                LDSM_X4_T(bh[nf2][0], bh[nf2][1], bh[nf2][2], bh[nf2][3], b0);
            }
            #pragma unroll
            for (int mf = 0; mf < 2; mf++)
                #pragma unroll
                for (int nf = 0; nf < 4; nf++) {
                    uint32_t* bhf = &bh[nf>>1][(nf&1)*2];
                    MMAF16(acc[mf][nf], ah[mf], bhf);
                }
        }

        CP_WAIT1();
        __syncthreads();
    }

    // epilogue: atomic add into out (commutative across K-quarters)
    #pragma unroll
    for (int mf = 0; mf < 2; mf++) {
        int r0 = j0 + wm*32 + mf*16 + (lane >> 2);
        #pragma unroll
        for (int nf = 0; nf < 4; nf++) {
            int c = wn*32 + nf*8 + (lane & 3)*2;
            size_t o0 = ((size_t)n*MM + r0)*DH + c;
            size_t o1 = o0 + (size_t)8*DH;
            atomicAdd(&out[o0],     acc[mf][nf][0]);
            atomicAdd(&out[o0 + 1], acc[mf][nf][1]);
            atomicAdd(&out[o1],     acc[mf][nf][2]);
            atomicAdd(&out[o1 + 1], acc[mf][nf][3]);
        }
    }
}

// ---------------------------------------------------------------------------
extern "C" void kernel_launch(void* const* d_in, const int* in_sizes, int n_in,
                              void* d_out, int out_size)
{
    const float* x    = (const float*)d_in[0];
    const float* edge = (const float*)d_in[1];
    const float* fw1  = (const float*)d_in[2];
    const float* fb1  = (const float*)d_in[3];
    const float* fw2  = (const float*)d_in[4];
    const float* fb2  = (const float*)d_in[5];
    const float* gw1  = (const float*)d_in[6];
    const float* gb1  = (const float*)d_in[7];
    const float* gw2  = (const float*)d_in[8];
    const float* gb2  = (const float*)d_in[9];
    float* out = (float*)d_out;

    const int SMEM1 = (4*W_PS + 2*A0_PS + 2*A1_PS) * 2;   // 96256 B (f-path max)
    const int SMEM2 = (3*SE_PS + 3*SG_PS) * 2;            // 39936 B

    cudaFuncSetAttribute(stage1_kernel, cudaFuncAttributeMaxDynamicSharedMemorySize, SMEM1);
    cudaFuncSetAttribute(stage2_kernel, cudaFuncAttributeMaxDynamicSharedMemorySize, SMEM2);

    prep_kernel<<<144, 256>>>(fw1, fw2, gw1, gw2);
    stage1_kernel<<<1024, S1_T, SMEM1>>>(x, fb1, fb2, gb1, gb2, out);
    stage2_kernel<<<dim3(32, NB, KSPLIT), 256, SMEM2>>>(edge, out);
}

// round 14
// speedup vs baseline: 1.1316x; 1.0203x over previous
#include <cuda_runtime.h>
#include <cuda_bf16.h>
#include <cuda_fp16.h>
#include <stdint.h>

#define NB   8
#define MM   2048
#define DIN  64
#define DH   128
#define NODES (NB*MM)
#define KSPLIT 4

// scratch for gx as fp16, layout [n][i][h]
__device__ __align__(16) __half g_gh[NODES * DH];

// prepped weights:
//   f1: split-bf16 COMPACT (64 x 72)
//   f2: split-bf16 full    (64 x 136)
//   g : single fp16        (0=g1c, 1=g2[0:64], 2=g2[64:128]), 64 x 136
#define W_LDT  136
#define W1_LDT 72
__device__ __align__(16) __nv_bfloat16 pw_f1hi[64 * W1_LDT];
__device__ __align__(16) __nv_bfloat16 pw_f1lo[64 * W1_LDT];
__device__ __align__(16) __nv_bfloat16 pw_f2hi[64 * W_LDT];
__device__ __align__(16) __nv_bfloat16 pw_f2lo[64 * W_LDT];
__device__ __align__(16) __half        pw_g [3][64 * W_LDT];

// ---------------------------------------------------------------------------
#define LDSM_X4(r0,r1,r2,r3,addr) \
    asm volatile("ldmatrix.sync.aligned.m8n8.x4.shared.b16 {%0,%1,%2,%3}, [%4];" \
        : "=r"(r0),"=r"(r1),"=r"(r2),"=r"(r3) : "r"(addr))
#define LDSM_X4_T(r0,r1,r2,r3,addr) \
    asm volatile("ldmatrix.sync.aligned.m8n8.x4.trans.shared.b16 {%0,%1,%2,%3}, [%4];" \
        : "=r"(r0),"=r"(r1),"=r"(r2),"=r"(r3) : "r"(addr))
#define MMA16816(c,a,b) \
    asm volatile("mma.sync.aligned.m16n8k16.row.col.f32.bf16.bf16.f32 " \
        "{%0,%1,%2,%3}, {%4,%5,%6,%7}, {%8,%9}, {%0,%1,%2,%3};" \
        : "+f"(c[0]),"+f"(c[1]),"+f"(c[2]),"+f"(c[3]) \
        : "r"(a[0]),"r"(a[1]),"r"(a[2]),"r"(a[3]),"r"(b[0]),"r"(b[1]))
#define MMAF16(c,a,b) \
    asm volatile("mma.sync.aligned.m16n8k16.row.col.f32.f16.f16.f32 " \
        "{%0,%1,%2,%3}, {%4,%5,%6,%7}, {%8,%9}, {%0,%1,%2,%3};" \
        : "+f"(c[0]),"+f"(c[1]),"+f"(c[2]),"+f"(c[3]) \
        : "r"(a[0]),"r"(a[1]),"r"(a[2]),"r"(a[3]),"r"(b[0]),"r"(b[1]))
#define CP_ASYNC16(dst,src) \
    asm volatile("cp.async.cg.shared.global [%0], [%1], 16;" :: "r"(dst), "l"(src))
#define CP_COMMIT() asm volatile("cp.async.commit_group;")
#define CP_WAIT0()  asm volatile("cp.async.wait_group 0;")
#define CP_WAIT1()  asm volatile("cp.async.wait_group 1;")

__device__ __forceinline__ void split2(float v0, float v1, uint32_t& hi, uint32_t& lo)
{
    __nv_bfloat16 h0 = __float2bfloat16(v0);
    __nv_bfloat16 h1 = __float2bfloat16(v1);
    __nv_bfloat16 l0 = __float2bfloat16(v0 - __bfloat162float(h0));
    __nv_bfloat16 l1 = __float2bfloat16(v1 - __bfloat162float(h1));
    hi = (uint32_t)__bfloat16_as_ushort(h0) | ((uint32_t)__bfloat16_as_ushort(h1) << 16);
    lo = (uint32_t)__bfloat16_as_ushort(l0) | ((uint32_t)__bfloat16_as_ushort(l1) << 16);
}

__device__ __forceinline__ uint32_t pack_h2(float a, float b)
{
    __half2 h = __floats2half2_rn(a, b);
    return *(uint32_t*)&h;
}

// ===========================================================================
// Weight prep.
// idx < 2048 : f1 (bf16 split, N=64, compact LDT=72)
// idx < 6144 : f2 (bf16 split, N=128, LDT=136)
// else       : g layers (fp16 single, N=128): gl = 0..2
// ===========================================================================
__global__ void prep_kernel(
    const float* __restrict__ fw1, const float* __restrict__ fw2,
    const float* __restrict__ gw1, const float* __restrict__ gw2)
{
    const int tot = 2048 + 4096 + 3*4096;   // 18432 col-pairs
    for (int idx = blockIdx.x*blockDim.x + threadIdx.x; idx < tot;
         idx += gridDim.x*blockDim.x) {
        if (idx < 2048) {                   // f1 compact
            int k  = idx >> 5;
            int n2 = (idx & 31) * 2;
            uint32_t hi, lo;
            split2(fw1[k*64 + n2], fw1[k*64 + n2 + 1], hi, lo);
            *(uint32_t*)&pw_f1hi[k*W1_LDT + n2] = hi;
            *(uint32_t*)&pw_f1lo[k*W1_LDT + n2] = lo;
        } else if (idx < 6144) {            // f2
            int rem = idx - 2048;
            int k  = rem >> 6;
            int n2 = (rem & 63) * 2;
            uint32_t hi, lo;
            split2(fw2[k*128 + n2], fw2[k*128 + n2 + 1], hi, lo);
            *(uint32_t*)&pw_f2hi[k*W_LDT + n2] = hi;
            *(uint32_t*)&pw_f2lo[k*W_LDT + n2] = lo;
        } else {                            // g layers fp16
            int r   = idx - 6144;
            int gl  = r >> 12;
            int rem = r & 4095;
            int k   = rem >> 6;
            int n2  = (rem & 63) * 2;
            float v0, v1;
            if (gl == 0) {
                v0 = gw1[k*128 + n2]     + gw1[(k + 64)*128 + n2];
                v1 = gw1[k*128 + n2 + 1] + gw1[(k + 64)*128 + n2 + 1];
            } else if (gl == 1) {
                v0 = gw2[k*128 + n2];        v1 = gw2[k*128 + n2 + 1];
            } else {
                v0 = gw2[(k + 64)*128 + n2]; v1 = gw2[(k + 64)*128 + n2 + 1];
            }
            *(uint32_t*)&pw_g[gl][k*W_LDT + n2] = pack_h2(v0, v1);
        }
    }
}

// ===========================================================================
// Stage 1 shared pieces. 128-thread blocks, 32 node-rows.
// ===========================================================================
#define S1_T   128
#define S1_R   32
#define A0_LDT 72
#define A1_LDT 136
#define W_PS   (64*W_LDT)
#define W1_PS  (64*W1_LDT)
#define A0_PS  (S1_R*A0_LDT)
#define A1_PS  (S1_R*A1_LDT)

template<int NFR>
__device__ __forceinline__ void mma_pass(
    float acc[2][NFR][4],
    uint32_t aHiA, uint32_t aLoA, int aLDT, int kColOfs,
    uint32_t wHiA, uint32_t wLoA, int wLDT,
    int lane, int wn)
{
    const int arow = lane & 15;
    const int aq   = ((lane >> 4) & 1) * 8;
    #pragma unroll
    for (int ks = 0; ks < 4; ks++) {
        uint32_t ah[2][4], al[2][4];
        #pragma unroll
        for (int mf = 0; mf < 2; mf++) {
            uint32_t ao = (uint32_t)(((arow + mf*16)*aLDT + kColOfs + ks*16 + aq) * 2);
            LDSM_X4(ah[mf][0], ah[mf][1], ah[mf][2], ah[mf][3], aHiA + ao);
            LDSM_X4(al[mf][0], al[mf][1], al[mf][2], al[mf][3], aLoA + ao);
        }
        uint32_t bh[(NFR+1)/2][4], bl[(NFR+1)/2][4];
        #pragma unroll
        for (int nf2 = 0; nf2 < (NFR+1)/2; nf2++) {
            uint32_t bo = (uint32_t)((((ks*16) + (lane & 15))*wLDT + wn*NFR*8 + nf2*16 + aq) * 2);
            LDSM_X4_T(bh[nf2][0], bh[nf2][1], bh[nf2][2], bh[nf2][3], wHiA + bo);
            LDSM_X4_T(bl[nf2][0], bl[nf2][1], bl[nf2][2], bl[nf2][3], wLoA + bo);
        }
        #pragma unroll
        for (int mf = 0; mf < 2; mf++)
            #pragma unroll
            for (int nf = 0; nf < NFR; nf++) {
                uint32_t* bhf = &bh[nf>>1][(nf&1)*2];
                uint32_t* blf = &bl[nf>>1][(nf&1)*2];
                MMA16816(acc[mf][nf], ah[mf], bhf);
                MMA16816(acc[mf][nf], ah[mf], blf);
                MMA16816(acc[mf][nf], al[mf], bhf);
            }
    }
}

// single-plane fp16 pass
template<int NFR>
__device__ __forceinline__ void mma_pass_f16(
    float acc[2][NFR][4],
    uint32_t aA, int aLDT, int kColOfs,
    uint32_t wA,
    int lane, int wn)
{
    const int arow = lane & 15;
    const int aq   = ((lane >> 4) & 1) * 8;
    #pragma unroll
    for (int ks = 0; ks < 4; ks++) {
        uint32_t ah[2][4];
        #pragma unroll
        for (int mf = 0; mf < 2; mf++) {
            uint32_t ao = (uint32_t)(((arow + mf*16)*aLDT + kColOfs + ks*16 + aq) * 2);
            LDSM_X4(ah[mf][0], ah[mf][1], ah[mf][2], ah[mf][3], aA + ao);
        }
        uint32_t bh[(NFR+1)/2][4];
        #pragma unroll
        for (int nf2 = 0; nf2 < (NFR+1)/2; nf2++) {
            uint32_t bo = (uint32_t)((((ks*16) + (lane & 15))*W_LDT + wn*NFR*8 + nf2*16 + aq) * 2);
            LDSM_X4_T(bh[nf2][0], bh[nf2][1], bh[nf2][2], bh[nf2][3], wA + bo);
        }
        #pragma unroll
        for (int mf = 0; mf < 2; mf++)
            #pragma unroll
            for (int nf = 0; nf < NFR; nf++) {
                uint32_t* bhf = &bh[nf>>1][(nf&1)*2];
                MMAF16(acc[mf][nf], ah[mf], bhf);
            }
    }
}

template<int NFR>
__device__ __forceinline__ void init_bias(float acc[2][NFR][4],
    const float* __restrict__ b, int lane, int wn)
{
    #pragma unroll
    for (int nf = 0; nf < NFR; nf++) {
        int c = wn*NFR*8 + nf*8 + (lane & 3)*2;
        float b0 = b[c], b1 = b[c + 1];
        #pragma unroll
        for (int mf = 0; mf < 2; mf++) {
            acc[mf][nf][0] = b0; acc[mf][nf][1] = b1;
            acc[mf][nf][2] = b0; acc[mf][nf][3] = b1;
        }
    }
}

template<int NFR>
__device__ __forceinline__ void epi_relu_split(float acc[2][NFR][4],
    __nv_bfloat16* dHi, __nv_bfloat16* dLo, int ldt, int lane, int wn)
{
    #pragma unroll
    for (int mf = 0; mf < 2; mf++) {
        int r0 = mf*16 + (lane >> 2);
        #pragma unroll
        for (int nf = 0; nf < NFR; nf++) {
            int c = wn*NFR*8 + nf*8 + (lane & 3)*2;
            uint32_t hi, lo;
            split2(fmaxf(acc[mf][nf][0], 0.f), fmaxf(acc[mf][nf][1], 0.f), hi, lo);
            *(uint32_t*)&dHi[r0*ldt + c] = hi;
            *(uint32_t*)&dLo[r0*ldt + c] = lo;
            split2(fmaxf(acc[mf][nf][2], 0.f), fmaxf(acc[mf][nf][3], 0.f), hi, lo);
            *(uint32_t*)&dHi[(r0 + 8)*ldt + c] = hi;
            *(uint32_t*)&dLo[(r0 + 8)*ldt + c] = lo;
        }
    }
}

template<int NFR>
__device__ __forceinline__ void epi_relu_f16(float acc[2][NFR][4],
    __half* d, int ldt, int lane, int wn)
{
    #pragma unroll
    for (int mf = 0; mf < 2; mf++) {
        int r0 = mf*16 + (lane >> 2);
        #pragma unroll
        for (int nf = 0; nf < NFR; nf++) {
            int c = wn*NFR*8 + nf*8 + (lane & 3)*2;
            *(uint32_t*)&d[r0*ldt + c] =
                pack_h2(fmaxf(acc[mf][nf][0], 0.f), fmaxf(acc[mf][nf][1], 0.f));
            *(uint32_t*)&d[(r0 + 8)*ldt + c] =
                pack_h2(fmaxf(acc[mf][nf][2], 0.f), fmaxf(acc[mf][nf][3], 0.f));
        }
    }
}

// issue-only async copy of a two-plane weight buffer; 1 group
__device__ __forceinline__ void weight_issue2(const void* srcH_, const void* srcL_,
    uint32_t wHiA, uint32_t wLoA, int bytes, int t)
{
    const uint8_t* srcH = (const uint8_t*)srcH_;
    const uint8_t* srcL = (const uint8_t*)srcL_;
    for (int idx = t; idx < bytes/16; idx += S1_T) {
        CP_ASYNC16(wHiA + idx*16, srcH + idx*16);
        CP_ASYNC16(wLoA + idx*16, srcL + idx*16);
    }
    CP_COMMIT();
}

// issue-only async copy of a single fp16 weight plane; 1 group
__device__ __forceinline__ void weight_issue_g(int layer, uint32_t wA, int t)
{
    const uint8_t* src = (const uint8_t*)pw_g[layer];
    for (int idx = t; idx < (64*W_LDT*2)/16; idx += S1_T)     // 1088
        CP_ASYNC16(wA + idx*16, src + idx*16);
    CP_COMMIT();
}

// ===========================================================================
// Stage 1 F: split-bf16 3-term, compact f1/a1 planes. 72 KB smem -> 3 CTA/SM.
// ===========================================================================
__global__ __launch_bounds__(S1_T) void stage1_f_kernel(
    const float* __restrict__ x,
    const float* __restrict__ fb1, const float* __restrict__ fb2,
    float* __restrict__ out)
{
    extern __shared__ __nv_bfloat16 s1[];
    __nv_bfloat16* wAHi = s1;                   // f1 compact: 64*72
    __nv_bfloat16* wALo = wAHi + W1_PS;
    __nv_bfloat16* wBHi = wALo + W1_PS;         // f2: 64*136
    __nv_bfloat16* wBLo = wBHi + W_PS;
    __nv_bfloat16* a0Hi = wBLo + W_PS;          // 32*72
    __nv_bfloat16* a0Lo = a0Hi + A0_PS;
    __nv_bfloat16* a1Hi = a0Lo + A0_PS;         // 32*72 (compact, 64 cols)
    __nv_bfloat16* a1Lo = a1Hi + A0_PS;
    const uint32_t wAHiA = (uint32_t)__cvta_generic_to_shared(wAHi);
    const uint32_t wALoA = (uint32_t)__cvta_generic_to_shared(wALo);
    const uint32_t wBHiA = (uint32_t)__cvta_generic_to_shared(wBHi);
    const uint32_t wBLoA = (uint32_t)__cvta_generic_to_shared(wBLo);
    const uint32_t a0HiA = (uint32_t)__cvta_generic_to_shared(a0Hi);
    const uint32_t a0LoA = (uint32_t)__cvta_generic_to_shared(a0Lo);
    const uint32_t a1HiA = (uint32_t)__cvta_generic_to_shared(a1Hi);
    const uint32_t a1LoA = (uint32_t)__cvta_generic_to_shared(a1Lo);

    const int t = threadIdx.x, lane = t & 31, wid = t >> 5;
    const int wn = wid & 3;
    const int nodeBase = blockIdx.x * S1_R;

    weight_issue2(pw_f1hi, pw_f1lo, wAHiA, wALoA, 64*W1_LDT*2, t);  // grp0
    weight_issue2(pw_f2hi, pw_f2lo, wBHiA, wBLoA, 64*W_LDT*2, t);   // grp1

    // x tile [32 x 64] split bf16
    for (int idx = t; idx < S1_R*64/2; idx += S1_T) {
        int r  = idx >> 5;
        int c2 = (idx & 31) * 2;
        float2 v = *(const float2*)&x[(size_t)(nodeBase + r)*DIN + c2];
        uint32_t hi, lo;
        split2(v.x, v.y, hi, lo);
        *(uint32_t*)&a0Hi[r*A0_LDT + c2] = hi;
        *(uint32_t*)&a0Lo[r*A0_LDT + c2] = lo;
    }

    CP_WAIT1();
    __syncthreads();
    {   // f1 (wA compact)
        float acc[2][2][4];
        init_bias<2>(acc, fb1, lane, wn);
        mma_pass<2>(acc, a0HiA, a0LoA, A0_LDT, 0, wAHiA, wALoA, W1_LDT, lane, wn);
        epi_relu_split<2>(acc, a1Hi, a1Lo, A0_LDT, lane, wn);
    }
    CP_WAIT0();
    __syncthreads();
    {   // f2 (wB) -> out
        float acc[2][4][4];
        init_bias<4>(acc, fb2, lane, wn);
        mma_pass<4>(acc, a1HiA, a1LoA, A0_LDT, 0, wBHiA, wBLoA, W_LDT, lane, wn);
        #pragma unroll
        for (int mf = 0; mf < 2; mf++) {
            int r0 = nodeBase + mf*16 + (lane >> 2);
            #pragma unroll
            for (int nf = 0; nf < 4; nf++) {
                int c = wn*32 + nf*8 + (lane & 3)*2;
                *(float2*)&out[(size_t)r0*DH + c]       = make_float2(acc[mf][nf][0], acc[mf][nf][1]);
                *(float2*)&out[(size_t)(r0 + 8)*DH + c] = make_float2(acc[mf][nf][2], acc[mf][nf][3]);
            }
        }
    }
}

// ===========================================================================
// Stage 1 G: pure fp16 single-term. 48 KB smem -> 4 CTA/SM, single wave.
// ===========================================================================
__global__ __launch_bounds__(S1_T) void stage1_g_kernel(
    const float* __restrict__ x,
    const float* __restrict__ gb1, const float* __restrict__ gb2)
{
    extern __shared__ __half sg[];
    __half* wGa = sg;                    // 64*136
    __half* wGb = wGa + W_PS;            // 64*136
    __half* a0h = wGb + W_PS;            // 32*72
    __half* a1h = a0h + A0_PS;           // 32*136
    const uint32_t wGaA = (uint32_t)__cvta_generic_to_shared(wGa);
    const uint32_t wGbA = (uint32_t)__cvta_generic_to_shared(wGb);
    const uint32_t a0hA = (uint32_t)__cvta_generic_to_shared(a0h);
    const uint32_t a1hA = (uint32_t)__cvta_generic_to_shared(a1h);

    const int t = threadIdx.x, lane = t & 31, wid = t >> 5;
    const int wn = wid & 3;
    const int nodeBase = blockIdx.x * S1_R;

    weight_issue_g(0, wGaA, t);   // grp0: g1c
    weight_issue_g(1, wGbA, t);   // grp1: g2 rows 0..63

    // x tile [32 x 64] fp16
    for (int idx = t; idx < S1_R*64/2; idx += S1_T) {
        int r  = idx >> 5;
        int c2 = (idx & 31) * 2;
        float2 v = *(const float2*)&x[(size_t)(nodeBase + r)*DIN + c2];
        *(uint32_t*)&a0h[r*A0_LDT + c2] = pack_h2(v.x, v.y);
    }

    CP_WAIT1();
    __syncthreads();
    {   // g1 (wGa)
        float acc[2][4][4];
        init_bias<4>(acc, gb1, lane, wn);
        mma_pass_f16<4>(acc, a0hA, A0_LDT, 0, wGaA, lane, wn);
        epi_relu_f16<4>(acc, a1h, A1_LDT, lane, wn);
    }
    __syncthreads();               // a1h visible; all warps done with wGa
    weight_issue_g(2, wGaA, t);    // grp2: g2 rows 64..127 -> wGa

    float acc[2][4][4];
    init_bias<4>(acc, gb2, lane, wn);
    CP_WAIT1();                    // grp1 arrived
    __syncthreads();
    mma_pass_f16<4>(acc, a1hA, A1_LDT, 0, wGbA, lane, wn);
    CP_WAIT0();                    // grp2 arrived (covered by g2a)
    __syncthreads();
    mma_pass_f16<4>(acc, a1hA, A1_LDT, 64, wGaA, lane, wn);

    // epilogue: fp16 -> g_gh [n][i][h] (coalesced)
    #pragma unroll
    for (int mf = 0; mf < 2; mf++) {
        int r0 = nodeBase + mf*16 + (lane >> 2);
        #pragma unroll
        for (int nf = 0; nf < 4; nf++) {
            int c = wn*32 + nf*8 + (lane & 3)*2;
            *(uint32_t*)&g_gh[(size_t)r0*DH + c] =
                pack_h2(acc[mf][nf][0], acc[mf][nf][1]);
            *(uint32_t*)&g_gh[(size_t)(r0 + 8)*DH + c] =
                pack_h2(acc[mf][nf][2], acc[mf][nf][3]);
        }
    }
}

// ===========================================================================
// Stage 2 (pure fp16 1-term, 3-stage pipeline) — unchanged from R13:
// out[n,j,h] += sum_i edge[n,i,j]*gx[n,i,h]
// grid (32, 8, KSPLIT=4): BM=64 x BN=128, BK=32.
// ===========================================================================
#define BK    32
#define EPAD  72
#define GPAD  136
#define SE_PS (BK*EPAD)
#define SG_PS (BK*GPAD)
#define KITER (MM/(BK*KSPLIT))     // 16

__global__ __launch_bounds__(256) void stage2_kernel(
    const float* __restrict__ edge, float* __restrict__ out)
{
    extern __shared__ __half sm2[];
    __half* sE = sm2;                   // [3 buf][BK][EPAD]
    __half* sG = sm2 + 3*SE_PS;         // [3 buf][BK][GPAD]

    const int n  = blockIdx.y;
    const int j0 = blockIdx.x * 64;
    const int kz = blockIdx.z;
    const int koff = kz * (MM / KSPLIT);
    const int t = threadIdx.x, lane = t & 31, wid = t >> 5;
    const int wm = wid >> 2, wn = wid & 3;

    const float* eg = edge + (size_t)n*MM*MM + j0;
    const __half* gh = g_gh + (size_t)n*MM*DH;

    const uint32_t sEb = (uint32_t)__cvta_generic_to_shared(sE);
    const uint32_t sGb = (uint32_t)__cvta_generic_to_shared(sG);

    const int ldrow = t >> 4;
    const int ecol  = (t & 15) * 4;
    const int gcol  = (t & 15) * 8;

    const int arow_off = ((lane >> 4) & 1)*8 + (lane & 7);
    const int aq1      = ((lane >> 3) & 1)*8;
    const int bq       = ((lane >> 4) & 1)*8;

    float acc[2][4][4];
    #pragma unroll
    for (int a = 0; a < 2; a++)
        #pragma unroll
        for (int b = 0; b < 4; b++)
            #pragma unroll
            for (int c = 0; c < 4; c++) acc[a][b][c] = 0.f;

    float4 erA[2], erB[2];

    // ---- prologue ----
    #pragma unroll
    for (int c = 0; c < 2; c++) {
        #pragma unroll
        for (int u = 0; u < 2; u++) {
            int row = ldrow + u*16;
            CP_ASYNC16(sGb + (uint32_t)((c*BK + row)*GPAD + gcol)*2,
                       gh + (size_t)(koff + c*BK + row)*DH + gcol);
        }
        CP_COMMIT();
    }
    #pragma unroll
    for (int u = 0; u < 2; u++)
        erA[u] = *(const float4*)&eg[(size_t)(koff + ldrow + u*16)*MM + ecol];
    #pragma unroll
    for (int u = 0; u < 2; u++) {
        int row = ldrow + u*16;
        float4 v = erA[u];
        *(uint2*)&sE[(0*BK + row)*EPAD + ecol] =
            make_uint2(pack_h2(v.x, v.y), pack_h2(v.z, v.w));
    }
    #pragma unroll
    for (int u = 0; u < 2; u++)
        erA[u] = *(const float4*)&eg[(size_t)(koff + 1*BK + ldrow + u*16)*MM + ecol];
    #pragma unroll
    for (int u = 0; u < 2; u++)
        erB[u] = *(const float4*)&eg[(size_t)(koff + 2*BK + ldrow + u*16)*MM + ecol];

    CP_WAIT1();
    __syncthreads();

    for (int kt = 0; kt < KITER; kt++) {
        const int b = kt % 3;

        if (kt + 2 < KITER) {
            const int i0 = koff + (kt + 2) * BK;
            const int gb = (kt + 2) % 3;
            #pragma unroll
            for (int u = 0; u < 2; u++) {
                int row = ldrow + u*16;
                CP_ASYNC16(sGb + (uint32_t)((gb*BK + row)*GPAD + gcol)*2,
                           gh + (size_t)(i0 + row)*DH + gcol);
            }
            CP_COMMIT();
        }

        if (kt + 1 < KITER) {
            const int eb = (kt + 1) % 3;
            #pragma unroll
            for (int u = 0; u < 2; u++) {
                int row = ldrow + u*16;
                float4 v = erA[u];
                *(uint2*)&sE[(eb*BK + row)*EPAD + ecol] =
                    make_uint2(pack_h2(v.x, v.y), pack_h2(v.z, v.w));
            }
        }

        erA[0] = erB[0]; erA[1] = erB[1];
        if (kt + 3 < KITER) {
            const int i0 = koff + (kt + 3) * BK;
            #pragma unroll
            for (int u = 0; u < 2; u++)
                erB[u] = *(const float4*)&eg[(size_t)(i0 + ldrow + u*16)*MM + ecol];
        }

        #pragma unroll
        for (int ks = 0; ks < BK; ks += 16) {
            uint32_t ah[2][4];
            #pragma unroll
            for (int mf = 0; mf < 2; mf++) {
                int acol = wm*32 + mf*16 + aq1;
                uint32_t a0 = sEb + (uint32_t)(((b*BK + ks + arow_off)*EPAD + acol)*2);
                LDSM_X4_T(ah[mf][0], ah[mf][1], ah[mf][2], ah[mf][3], a0);
            }
            uint32_t bh[2][4];
            #pragma unroll
            for (int nf2 = 0; nf2 < 2; nf2++) {
                int bcol = wn*32 + nf2*16 + bq;
                uint32_t b0 = sGb + (uint32_t)(((b*BK + ks + (lane & 15))*GPAD + bcol)*2);
                LDSM_X4_T(bh[nf2][0], bh[nf2][1], bh[nf2][2], bh[nf2][3], b0);
            }
            #pragma unroll
            for (int mf = 0; mf < 2; mf++)
                #pragma unroll
                for (int nf = 0; nf < 4; nf++) {
                    uint32_t* bhf = &bh[nf>>1][(nf&1)*2];
                    MMAF16(acc[mf][nf], ah[mf], bhf);
                }
        }

        CP_WAIT1();
        __syncthreads();
    }

    // epilogue: atomic add into out (commutative across K-quarters)
    #pragma unroll
    for (int mf = 0; mf < 2; mf++) {
        int r0 = j0 + wm*32 + mf*16 + (lane >> 2);
        #pragma unroll
        for (int nf = 0; nf < 4; nf++) {
            int c = wn*32 + nf*8 + (lane & 3)*2;
            size_t o0 = ((size_t)n*MM + r0)*DH + c;
            size_t o1 = o0 + (size_t)8*DH;
            atomicAdd(&out[o0],     acc[mf][nf][0]);
            atomicAdd(&out[o0 + 1], acc[mf][nf][1]);
            atomicAdd(&out[o1],     acc[mf][nf][2]);
            atomicAdd(&out[o1 + 1], acc[mf][nf][3]);
        }
    }
}

// ---------------------------------------------------------------------------
extern "C" void kernel_launch(void* const* d_in, const int* in_sizes, int n_in,
                              void* d_out, int out_size)
{
    const float* x    = (const float*)d_in[0];
    const float* edge = (const float*)d_in[1];
    const float* fw1  = (const float*)d_in[2];
    const float* fb1  = (const float*)d_in[3];
    const float* fw2  = (const float*)d_in[4];
    const float* fb2  = (const float*)d_in[5];
    const float* gw1  = (const float*)d_in[6];
    const float* gb1  = (const float*)d_in[7];
    const float* gw2  = (const float*)d_in[8];
    const float* gb2  = (const float*)d_in[9];
    float* out = (float*)d_out;

    const int SMEM_F = (2*W1_PS + 2*W_PS + 4*A0_PS) * 2;   // 71680 B -> 3 CTA/SM
    const int SMEM_G = (2*W_PS + A0_PS + A1_PS) * 2;       // 48128 B -> 4 CTA/SM
    const int SMEM2  = (3*SE_PS + 3*SG_PS) * 2;            // 39936 B

    cudaFuncSetAttribute(stage1_f_kernel, cudaFuncAttributeMaxDynamicSharedMemorySize, SMEM_F);
    cudaFuncSetAttribute(stage1_g_kernel, cudaFuncAttributeMaxDynamicSharedMemorySize, SMEM_G);
    cudaFuncSetAttribute(stage2_kernel,   cudaFuncAttributeMaxDynamicSharedMemorySize, SMEM2);

    prep_kernel<<<144, 256>>>(fw1, fw2, gw1, gw2);
    stage1_g_kernel<<<512, S1_T, SMEM_G>>>(x, gb1, gb2);
    stage1_f_kernel<<<512, S1_T, SMEM_F>>>(x, fb1, fb2, out);
    stage2_kernel<<<dim3(32, NB, KSPLIT), 256, SMEM2>>>(edge, out);
}